// round 15
// baseline (speedup 1.0000x reference)
#include <cuda_runtime.h>
#include <cuda_fp16.h>
#include <cstdint>

// GPTQLinear via warp-level mma.sync (m16n8k16 fp16, fp32 accum), exact-integer weights.
// out[b,o] = sum_g s[o,g]*(P[o,b,g] - z[o,g]*Xs[b,g]) + bias[o]
//   P = sum_{k in g} q[o,k]*fp16(x[b,k])   (exact: q in [0,15] is exact in fp16)
//   Xs[b,g] = sum_{k in g} fp16(x[b,k])
// Fused: each CTA builds its own B-fragment table + Xs + scale tables in smem.

#define OUTF  11008
#define INF   4096
#define NB    16
#define QI    2048          // int32 (one packed byte each) per O-row
#define NG    32
#define THREADS 128
#define KSPLIT 8
#define GRID  (86 * KSPLIT)                 // 86 O-tiles(128 rows) x 8 K-splits

__device__ float g_part[KSPLIT * NB * OUTF];

// byte (2 nibbles) -> f16x2 {lo nibble, hi nibble}, exact
__device__ __forceinline__ unsigned cvt4(int bv) {
    unsigned h = ((unsigned)(bv | (bv << 12)) & 0x000F000Fu) | 0x64006400u;
    unsigned r;
    asm("sub.f16x2 %0, %1, %2;" : "=r"(r) : "r"(h), "r"(0x64006400u));
    return r;
}

#define MMA(d, a0, a1, a2, a3, b0, b1) \
    asm volatile("mma.sync.aligned.m16n8k16.row.col.f32.f16.f16.f32 " \
        "{%0,%1,%2,%3}, {%4,%5,%6,%7}, {%8,%9}, {%0,%1,%2,%3};" \
        : "+f"((d)[0]), "+f"((d)[1]), "+f"((d)[2]), "+f"((d)[3]) \
        : "r"(a0), "r"(a1), "r"(a2), "r"(a3), "r"(b0), "r"(b1))

// ---------------- main: fused prep + register-resident dequant + mma.sync ----------------
__global__ __launch_bounds__(THREADS)
void gptq_mma_kernel(const int* __restrict__ qw,
                     const float* __restrict__ x,
                     const float* __restrict__ scales,
                     const float* __restrict__ zeros) {
    __shared__ uint4  s_xf[1024];      // 16KB: [gl*4+t][half][lane] B fragments
    __shared__ float4 s_sc4[128];      // scales[o0+row][G0..G0+3]
    __shared__ float4 s_zr4[128];      // zeros [o0+row][G0..G0+3]
    __shared__ float  s_Xs[64];        // [b][gl]

    const int tid = threadIdx.x, lane = tid & 31, warp = tid >> 5;
    const int kq = blockIdx.x & (KSPLIT - 1), ot = blockIdx.x / KSPLIT;
    const int G0 = kq * 4;
    const int o0 = ot * 128;
    const int o_base = o0 + warp * 32;
    const int q = lane & 3, rowg = lane >> 2;

    // ---- prologue: B-fragment slice (8 entries/thread, coalesced x reads) ----
#pragma unroll
    for (int i = 0; i < 8; ++i) {
        int e = tid + i * THREADS;                    // 0..1023
        int le = e & 31, half = (e >> 5) & 1, gt = e >> 6;
        int gl = gt >> 2, t = gt & 3, qq = le & 3;
        int b = (le >> 2) + 8 * half;
        const float* xp = x + b * INF + (G0 + gl) * 128 + 32 * t + 8 * qq;
        float4 v0 = *reinterpret_cast<const float4*>(xp);
        float4 v1 = *reinterpret_cast<const float4*>(xp + 4);
        uint4 o;
        __half2 h;
        h = __floats2half2_rn(v0.x, v0.y); o.x = *reinterpret_cast<unsigned*>(&h);
        h = __floats2half2_rn(v0.z, v0.w); o.y = *reinterpret_cast<unsigned*>(&h);
        h = __floats2half2_rn(v1.x, v1.y); o.z = *reinterpret_cast<unsigned*>(&h);
        h = __floats2half2_rn(v1.z, v1.w); o.w = *reinterpret_cast<unsigned*>(&h);
        s_xf[e] = o;
    }
    // scale/zero tables: one coalesced LDG.128 per thread each
    s_sc4[tid] = *reinterpret_cast<const float4*>(scales + (o0 + tid) * NG + G0);
    s_zr4[tid] = *reinterpret_cast<const float4*>(zeros  + (o0 + tid) * NG + G0);
    __syncthreads();

    // ---- Xs from smem fragments (fp32 accumulation of fp16 values) ----
    {
        int p = tid >> 1, hs = tid & 1;               // pair p = b*4+gl
        int b = p >> 2, gl = p & 3;
        int lx = 4 * (b & 7), hf = b >> 3;
        float sum = 0.f;
#pragma unroll
        for (int t2 = 0; t2 < 2; ++t2) {
            int t = 2 * hs + t2;
#pragma unroll
            for (int qq = 0; qq < 4; ++qq) {
                uint4 u = s_xf[(gl * 4 + t) * 64 + hf * 32 + lx + qq];
#pragma unroll
                for (int m = 0; m < 4; ++m) {
                    __half2 h2 = *reinterpret_cast<__half2*>(&(&u.x)[m]);
                    float2 f = __half22float2(h2);
                    sum += f.x + f.y;
                }
            }
        }
        sum += __shfl_xor_sync(0xffffffffu, sum, 1);
        if (hs == 0) s_Xs[p] = sum;
    }
    __syncthreads();

    const float* s_sc = reinterpret_cast<const float*>(s_sc4);
    const float* s_zr = reinterpret_cast<const float*>(s_zr4);

    // qweight row pointers: r = mt*2 + rowhalf -> row o_base + r*8 + rowg
    const int4* qp[4];
#pragma unroll
    for (int r = 0; r < 4; ++r)
        qp[r] = reinterpret_cast<const int4*>(qw + (o_base + r * 8 + rowg) * QI);

    float acc[16];                    // [mt][half][4]
#pragma unroll
    for (int i = 0; i < 16; ++i) acc[i] = 0.f;

#pragma unroll
    for (int g = 0; g < 4; ++g) {
        const int G = G0 + g;
        float P[16];
#pragma unroll
        for (int i = 0; i < 16; ++i) P[i] = 0.f;

#pragma unroll
        for (int t = 0; t < 4; ++t) {
            const uint4* bf = s_xf + (g * 4 + t) * 64 + lane;
            uint4 u0 = bf[0];         // batches 0-7, this k-slice
            uint4 u1 = bf[32];        // batches 8-15
            const int qi = G * 16 + 4 * t + q;    // 64B-contiguous across lanes q=0..3
#pragma unroll
            for (int mt = 0; mt < 2; ++mt) {
                int4 vL = qp[mt * 2][qi];       // row lo
                int4 vH = qp[mt * 2 + 1][qi];   // row hi (+8)
                unsigned aL0 = cvt4(vL.x), aH0 = cvt4(vH.x);
                unsigned aL1 = cvt4(vL.y), aH1 = cvt4(vH.y);
                MMA(P + mt * 8,     aL0, aH0, aL1, aH1, u0.x, u0.y);
                MMA(P + mt * 8 + 4, aL0, aH0, aL1, aH1, u1.x, u1.y);
                unsigned bL0 = cvt4(vL.z), bH0 = cvt4(vH.z);
                unsigned bL1 = cvt4(vL.w), bH1 = cvt4(vH.w);
                MMA(P + mt * 8,     bL0, bH0, bL1, bH1, u0.z, u0.w);
                MMA(P + mt * 8 + 4, bL0, bH0, bL1, bH1, u1.z, u1.w);
            }
        }

        // epilogue: per-group rescale in fp32 (tables in smem)
#pragma unroll
        for (int mt = 0; mt < 2; ++mt) {
            int rL = warp * 32 + mt * 16 + rowg;      // local row
            float sL = s_sc[rL * 4 + g],       zL = s_zr[rL * 4 + g];
            float sH = s_sc[(rL + 8) * 4 + g], zH = s_zr[(rL + 8) * 4 + g];
#pragma unroll
            for (int h = 0; h < 2; ++h) {
                int bb = 2 * q + 8 * h;
                float X0 = s_Xs[bb * 4 + g], X1 = s_Xs[(bb + 1) * 4 + g];
                float* Pp = P + mt * 8 + h * 4;
                float* ap = acc + mt * 8 + h * 4;
                ap[0] += sL * fmaf(-zL, X0, Pp[0]);
                ap[1] += sL * fmaf(-zL, X1, Pp[1]);
                ap[2] += sH * fmaf(-zH, X0, Pp[2]);
                ap[3] += sH * fmaf(-zH, X1, Pp[3]);
            }
        }
    }

    // store K-split partials
    float* dst = g_part + kq * (NB * OUTF);
#pragma unroll
    for (int mt = 0; mt < 2; ++mt) {
        int oL = o_base + mt * 16 + rowg, oH = oL + 8;
#pragma unroll
        for (int h = 0; h < 2; ++h) {
            int bb = 2 * q + 8 * h;
            float* ap = acc + mt * 8 + h * 4;
            dst[bb * OUTF + oL]       = ap[0];
            dst[(bb + 1) * OUTF + oL] = ap[1];
            dst[bb * OUTF + oH]       = ap[2];
            dst[(bb + 1) * OUTF + oH] = ap[3];
        }
    }
}

// ---------------- reduce: sum K-split partials + bias (vectorized) ----------------
__global__ void reduce_kernel(const float* __restrict__ bias, float* __restrict__ out) {
    int t4 = (blockIdx.x * 256 + threadIdx.x) * 4;   // 172*256*4 = NB*OUTF exactly
    int oc = t4 % OUTF;                              // OUTF % 4 == 0: no row crossing
    float4 v = *reinterpret_cast<const float4*>(bias + oc);
#pragma unroll
    for (int k = 0; k < KSPLIT; ++k) {
        float4 p = *reinterpret_cast<const float4*>(g_part + k * (NB * OUTF) + t4);
        v.x += p.x; v.y += p.y; v.z += p.z; v.w += p.w;
    }
    *reinterpret_cast<float4*>(out + t4) = v;
}

extern "C" void kernel_launch(void* const* d_in, const int* in_sizes, int n_in,
                              void* d_out, int out_size) {
    const float* x      = (const float*)d_in[0];
    const int*   qw     = (const int*)d_in[1];
    const float* scales = (const float*)d_in[2];
    const float* zeros  = (const float*)d_in[3];
    const float* bias   = (const float*)d_in[4];
    float*       out    = (float*)d_out;

    gptq_mma_kernel<<<GRID, THREADS>>>(qw, x, scales, zeros);
    reduce_kernel<<<172, 256>>>(bias, out);
}

// round 16
// speedup vs baseline: 1.1561x; 1.1561x over previous
#include <cuda_runtime.h>
#include <cuda_fp16.h>
#include <cstdint>

// GPTQLinear via warp-level mma.sync (m16n8k16 fp16, fp32 accum), exact-integer weights.
// out[b,o] = sum_g s[o,g]*(P[o,b,g] - z[o,g]*Xs[b,g]) + bias[o]
//   P = sum_{k in g} q[o,k]*fp16(x[b,k])   (exact: q in [0,15] is exact in fp16)
//   Xs[b,g] = sum_{k in g} fp16(x[b,k])

#define OUTF  11008
#define INF   4096
#define NB    16
#define QI    2048          // int32 (one packed byte each) per O-row
#define NG    32
#define THREADS 128
#define KSPLIT 4
#define TILE_O 64
#define GRID  ((OUTF / TILE_O) * KSPLIT)    // 172 O-tiles x 4 K-splits = 688

__device__ uint4 g_xfrag[128 * 2 * 32];     // [gt=G*4+t][half][lane]; 128KB
__device__ float g_Xs[NB * NG];             // [b][G]
__device__ float g_part[KSPLIT * NB * OUTF];

// byte (2 nibbles) -> f16x2 {lo nibble, hi nibble}, exact
__device__ __forceinline__ unsigned cvt4(int bv) {
    unsigned h = ((unsigned)(bv | (bv << 12)) & 0x000F000Fu) | 0x64006400u;
    unsigned r;
    asm("sub.f16x2 %0, %1, %2;" : "=r"(r) : "r"(h), "r"(0x64006400u));
    return r;
}

#define MMA(d, a0, a1, a2, a3, b0, b1) \
    asm volatile("mma.sync.aligned.m16n8k16.row.col.f32.f16.f16.f32 " \
        "{%0,%1,%2,%3}, {%4,%5,%6,%7}, {%8,%9}, {%0,%1,%2,%3};" \
        : "+f"((d)[0]), "+f"((d)[1]), "+f"((d)[2]), "+f"((d)[3]) \
        : "r"(a0), "r"(a1), "r"(a2), "r"(a3), "r"(b0), "r"(b1))

// ---------------- prep: B-fragment table + per-group fp16 x sums ----------------
// blocks [0,64): g_xfrag, one entry per thread (8192 entries).
// blocks [64,192): g_Xs, one warp per (b,g) pair (512 warps).
__global__ void prep_kernel(const float* __restrict__ x) {
    if (blockIdx.x < 64) {
        int e = blockIdx.x * 128 + threadIdx.x;       // 8192 entries
        int lane = e & 31, half = (e >> 5) & 1, gt = e >> 6;
        int G = gt >> 2, t = gt & 3, q = lane & 3;
        int b = (lane >> 2) + 8 * half;
        int c = G * 128 + 32 * t + 8 * q;             // k-permuted (matches main)
        const float* xp = x + b * INF + c;
        float4 v0 = *reinterpret_cast<const float4*>(xp);
        float4 v1 = *reinterpret_cast<const float4*>(xp + 4);
        uint4 o;
        __half2 h;
        h = __floats2half2_rn(v0.x, v0.y); o.x = *reinterpret_cast<unsigned*>(&h);
        h = __floats2half2_rn(v0.z, v0.w); o.y = *reinterpret_cast<unsigned*>(&h);
        h = __floats2half2_rn(v1.x, v1.y); o.z = *reinterpret_cast<unsigned*>(&h);
        h = __floats2half2_rn(v1.z, v1.w); o.w = *reinterpret_cast<unsigned*>(&h);
        g_xfrag[e] = o;
    } else {
        int w = (blockIdx.x - 64) * 4 + (threadIdx.x >> 5);   // 512 warps
        int lane = threadIdx.x & 31;
        int b = w >> 5, g = w & 31;
        float4 v = *reinterpret_cast<const float4*>(x + b * INF + g * 128 + lane * 4);
        float sum = __half2float(__float2half_rn(v.x))
                  + __half2float(__float2half_rn(v.y))
                  + __half2float(__float2half_rn(v.z))
                  + __half2float(__float2half_rn(v.w));
#pragma unroll
        for (int off = 16; off; off >>= 1)
            sum += __shfl_xor_sync(0xffffffffu, sum, off);
        if (lane == 0) g_Xs[b * NG + g] = sum;
    }
}

// ---------------- main: register-resident dequant + mma.sync ----------------
__global__ __launch_bounds__(THREADS)
void gptq_mma_kernel(const int* __restrict__ qw,
                     const float* __restrict__ scales,
                     const float* __restrict__ zeros) {
    const int tid = threadIdx.x, lane = tid & 31, warp = tid >> 5;
    const int kq = blockIdx.x & (KSPLIT - 1), ot = blockIdx.x / KSPLIT;
    const int G0 = kq * 8;
    const int o_base = ot * TILE_O + warp * 16;
    const int q = lane & 3, rowg = lane >> 2;

    // qweight row pointers: rows o_base + rowg and o_base + 8 + rowg
    const int4* qpL = reinterpret_cast<const int4*>(qw + (o_base + rowg) * QI);
    const int4* qpH = reinterpret_cast<const int4*>(qw + (o_base + 8 + rowg) * QI);

    float acc[8];                     // [half][4]
#pragma unroll
    for (int i = 0; i < 8; ++i) acc[i] = 0.f;

#pragma unroll
    for (int g = 0; g < 8; ++g) {
        const int G = G0 + g;
        float P[8];
#pragma unroll
        for (int i = 0; i < 8; ++i) P[i] = 0.f;

#pragma unroll
        for (int t = 0; t < 4; ++t) {
            const uint4* bf = g_xfrag + (G * 4 + t) * 64 + lane;
            uint4 u0 = bf[0];         // batches 0-7, this k-slice
            uint4 u1 = bf[32];        // batches 8-15
            const int qi = G * 16 + 4 * t + q;    // 64B-contiguous across lanes q=0..3
            int4 vL = qpL[qi];        // row lo
            int4 vH = qpH[qi];        // row hi (+8)
            unsigned aL0 = cvt4(vL.x), aH0 = cvt4(vH.x);
            unsigned aL1 = cvt4(vL.y), aH1 = cvt4(vH.y);
            MMA(P,     aL0, aH0, aL1, aH1, u0.x, u0.y);
            MMA(P + 4, aL0, aH0, aL1, aH1, u1.x, u1.y);
            unsigned bL0 = cvt4(vL.z), bH0 = cvt4(vH.z);
            unsigned bL1 = cvt4(vL.w), bH1 = cvt4(vH.w);
            MMA(P,     bL0, bH0, bL1, bH1, u0.z, u0.w);
            MMA(P + 4, bL0, bH0, bL1, bH1, u1.z, u1.w);
        }

        // epilogue: per-group rescale in fp32
        {
            int oL = o_base + rowg, oH = oL + 8;
            float sL = scales[oL * NG + G], zL = zeros[oL * NG + G];
            float sH = scales[oH * NG + G], zH = zeros[oH * NG + G];
#pragma unroll
            for (int h = 0; h < 2; ++h) {
                int bb = 2 * q + 8 * h;
                float X0 = g_Xs[bb * NG + G], X1 = g_Xs[(bb + 1) * NG + G];
                float* Pp = P + h * 4;
                float* ap = acc + h * 4;
                ap[0] += sL * fmaf(-zL, X0, Pp[0]);
                ap[1] += sL * fmaf(-zL, X1, Pp[1]);
                ap[2] += sH * fmaf(-zH, X0, Pp[2]);
                ap[3] += sH * fmaf(-zH, X1, Pp[3]);
            }
        }
    }

    // store K-split partials
    float* dst = g_part + kq * (NB * OUTF);
    int oL = o_base + rowg, oH = oL + 8;
#pragma unroll
    for (int h = 0; h < 2; ++h) {
        int bb = 2 * q + 8 * h;
        float* ap = acc + h * 4;
        dst[bb * OUTF + oL]       = ap[0];
        dst[(bb + 1) * OUTF + oL] = ap[1];
        dst[bb * OUTF + oH]       = ap[2];
        dst[(bb + 1) * OUTF + oH] = ap[3];
    }
}

// ---------------- reduce: sum K-split partials + bias (688 blocks, coalesced) ----------------
__global__ void reduce_kernel(const float* __restrict__ bias, float* __restrict__ out) {
    int t = blockIdx.x * 256 + threadIdx.x;          // 688*256 = NB*OUTF exactly
    int oc = t % OUTF;
    float v = bias[oc];
#pragma unroll
    for (int k = 0; k < KSPLIT; ++k) v += g_part[k * (NB * OUTF) + t];
    out[t] = v;
}

extern "C" void kernel_launch(void* const* d_in, const int* in_sizes, int n_in,
                              void* d_out, int out_size) {
    const float* x      = (const float*)d_in[0];
    const int*   qw     = (const int*)d_in[1];
    const float* scales = (const float*)d_in[2];
    const float* zeros  = (const float*)d_in[3];
    const float* bias   = (const float*)d_in[4];
    float*       out    = (float*)d_out;

    prep_kernel<<<192, 128>>>(x);
    gptq_mma_kernel<<<GRID, THREADS>>>(qw, scales, zeros);
    reduce_kernel<<<688, 256>>>(bias, out);
}